// round 2
// baseline (speedup 1.0000x reference)
#include <cuda_runtime.h>
#include <math.h>

typedef unsigned long long ull;

#define NNODE 307
#define NP    320
#define BATCH 512
#define CIN   5
#define HID   16
#define KORD  6
#define BH    8192          // BATCH*HID
#define BC    2560          // BATCH*CIN
#define NPBC  (NP*BC)

// ------------------------------ scratch ------------------------------------
__device__ float g_En[NNODE * 10];
__device__ float g_G[NNODE * NNODE];
__device__ float g_dinv[NNODE];
__device__ float g_L[NP * NP];
__device__ float g_Y[KORD * NPBC];
__device__ float g_SA[NP * BH];
__device__ float g_SB[NP * BH];
__device__ float g_T[NP * BH];
__device__ float g_U[NP * BH];

// ------------------------------ helpers ------------------------------------
__device__ __forceinline__ ull pack2(float x, float y) {
    ull d; asm("mov.b64 %0, {%1, %2};" : "=l"(d) : "f"(x), "f"(y)); return d;
}
__device__ __forceinline__ void unpack2(ull v, float& x, float& y) {
    asm("mov.b64 {%0, %1}, %2;" : "=f"(x), "=f"(y) : "l"(v));
}
__device__ __forceinline__ ull fma2(ull a, ull b, ull c) {
    ull d; asm("fma.rn.f32x2 %0, %1, %2, %3;" : "=l"(d) : "l"(a), "l"(b), "l"(c));
    return d;
}
// tanh(x) = 1 - 2/(e^{2x}+1), via MUFU ex2/rcp (exact identity, ~1e-6 err)
__device__ __forceinline__ float ftanh(float x) {
    float e; asm("ex2.approx.f32 %0, %1;" : "=f"(e) : "f"(x * 2.885390082f));
    float r; asm("rcp.approx.f32 %0, %1;" : "=f"(r) : "f"(e + 1.0f));
    return fmaf(-2.0f, r, 1.0f);
}
__device__ __forceinline__ float fsig(float x) {
    return fmaf(0.5f, ftanh(0.5f * x), 0.5f);
}

// ------------------------------ setup ---------------------------------------
__global__ void k_norm(const float* __restrict__ E) {
    int n = blockIdx.x * 64 + threadIdx.x;
    if (n < NNODE) {
        float s = 0.f;
#pragma unroll
        for (int c = 0; c < 10; c++) s += E[n * 10 + c] * E[n * 10 + c];
        float inv = rsqrtf(s);
#pragma unroll
        for (int c = 0; c < 10; c++) g_En[n * 10 + c] = E[n * 10 + c] * inv;
    }
}

__global__ void k_gram() {
    __shared__ float red[64];
    int n = blockIdx.x;
    float e[10];
#pragma unroll
    for (int c = 0; c < 10; c++) e[c] = g_En[n * 10 + c];
    float s = 0.f;
    for (int m = threadIdx.x; m < NNODE; m += 64) {
        float d = 0.f;
#pragma unroll
        for (int c = 0; c < 10; c++) d += e[c] * g_En[m * 10 + c];
        g_G[n * NNODE + m] = d;
        s += d;
    }
    red[threadIdx.x] = s;
    __syncthreads();
    for (int w = 32; w > 0; w >>= 1) {
        if (threadIdx.x < w) red[threadIdx.x] += red[threadIdx.x + w];
        __syncthreads();
    }
    if (threadIdx.x == 0) g_dinv[n] = rsqrtf(red[0]);
}

__global__ void k_lap() {
    int idx = blockIdx.x * 256 + threadIdx.x;
    if (idx >= NP * NP) return;
    int n = idx / NP, m = idx % NP;
    float v = 0.f;
    if (n < NNODE && m < NNODE) {
        float g = g_G[n * NNODE + m];
        v = ((n == m) ? 1.f : 0.f) - g_dinv[n] * g * g_dinv[m];
    }
    g_L[idx] = v;
}

__global__ void k_xt(const float* __restrict__ flow, float* __restrict__ Y0) {
    int idx = blockIdx.x * 128 + threadIdx.x;
    if (idx >= NP * BATCH) return;
    int n = idx >> 9, b = idx & 511;
#pragma unroll
    for (int c = 0; c < CIN; c++) {
        float v = 0.f;
        if (n < NNODE) v = flow[((size_t)b * NNODE + n) * CIN + c];
        Y0[(size_t)n * BC + b * CIN + c] = v;
    }
}

// ------------- generic: Cout = alpha*(L@Bin) + beta*Csub  (ld columns) ------
__global__ void __launch_bounds__(256) k_gemm(
    const float* __restrict__ Bin, const float* __restrict__ Csub,
    float* __restrict__ Cout, int ld, float alpha, float beta)
{
    __shared__ __align__(16) float As[16][72];
    __shared__ __align__(16) float Bs[16][72];
    int tid = threadIdx.x;
    int tx = tid & 15, ty = tid >> 4;
    int row0 = blockIdx.y << 6, col0 = blockIdx.x << 6;
    int a_r = tid >> 2, a_c4 = (tid & 3) << 2;
    int b_r = tid >> 4, b_c4 = (tid & 15) << 2;
    ull acc[4][2];
#pragma unroll
    for (int i = 0; i < 4; i++) { acc[i][0] = pack2(0.f, 0.f); acc[i][1] = pack2(0.f, 0.f); }
    const float* Ap = g_L + (size_t)(row0 + a_r) * NP + a_c4;
    const float* Bp = Bin + (size_t)b_r * ld + col0 + b_c4;
    for (int k0 = 0; k0 < NP; k0 += 16) {
        float4 av = *(const float4*)(Ap + k0);
        As[a_c4 + 0][a_r] = av.x; As[a_c4 + 1][a_r] = av.y;
        As[a_c4 + 2][a_r] = av.z; As[a_c4 + 3][a_r] = av.w;
        *(float4*)(&Bs[b_r][b_c4]) = *(const float4*)(Bp + (size_t)k0 * ld);
        __syncthreads();
#pragma unroll
        for (int kk = 0; kk < 16; kk++) {
            float4 a = *(const float4*)(&As[kk][ty << 2]);
            ulonglong2 bb = *(const ulonglong2*)(&Bs[kk][tx << 2]);
            ull a0 = pack2(a.x, a.x), a1 = pack2(a.y, a.y);
            ull a2 = pack2(a.z, a.z), a3 = pack2(a.w, a.w);
            acc[0][0] = fma2(a0, bb.x, acc[0][0]); acc[0][1] = fma2(a0, bb.y, acc[0][1]);
            acc[1][0] = fma2(a1, bb.x, acc[1][0]); acc[1][1] = fma2(a1, bb.y, acc[1][1]);
            acc[2][0] = fma2(a2, bb.x, acc[2][0]); acc[2][1] = fma2(a2, bb.y, acc[2][1]);
            acc[3][0] = fma2(a3, bb.x, acc[3][0]); acc[3][1] = fma2(a3, bb.y, acc[3][1]);
        }
        __syncthreads();
    }
#pragma unroll
    for (int i = 0; i < 4; i++) {
        int row = row0 + (ty << 2) + i;
        float v[4];
        unpack2(acc[i][0], v[0], v[1]);
        unpack2(acc[i][1], v[2], v[3]);
#pragma unroll
        for (int j = 0; j < 4; j++) {
            int col = col0 + (tx << 2) + j;
            size_t o = (size_t)row * ld + col;
            Cout[o] = alpha * v[j] + beta * Csub[o];
        }
    }
}

// -------- combine: SB = sum_k Y_k @ cheb_w[k] + cheb_b ; SA = Y_0 @ cou_w ---
__global__ void __launch_bounds__(128) k_combine(
    const float* __restrict__ cheb_w, const float* __restrict__ cheb_b,
    const float* __restrict__ cou_w, const float* __restrict__ Y,
    float* __restrict__ SA, float* __restrict__ SB)
{
    __shared__ float scw[KORD * CIN * HID];
    __shared__ float scb[HID];
    __shared__ float sco[CIN * HID];
    int tid = threadIdx.x;
    for (int i = tid; i < KORD * CIN * HID; i += 128) scw[i] = cheb_w[i];
    if (tid < HID) scb[tid] = cheb_b[tid];
    if (tid < CIN * HID) sco[tid] = cou_w[tid];
    __syncthreads();
    int idx = blockIdx.x * 128 + tid;
    if (idx >= NP * BATCH) return;
    int n = idx >> 9, b = idx & 511;
    size_t base = (size_t)n * BH + (b << 4);
    if (n >= NNODE) {
#pragma unroll
        for (int h = 0; h < 16; h++) { SA[base + h] = 0.f; SB[base + h] = 0.f; }
        return;
    }
    float o[16], p[16];
#pragma unroll
    for (int h = 0; h < 16; h++) { o[h] = scb[h]; p[h] = 0.f; }
#pragma unroll
    for (int k = 0; k < KORD; k++) {
#pragma unroll
        for (int c = 0; c < CIN; c++) {
            float y = Y[(size_t)k * NPBC + (size_t)n * BC + b * CIN + c];
            const float* w = &scw[(k * CIN + c) * HID];
#pragma unroll
            for (int h = 0; h < 16; h++) o[h] = fmaf(y, w[h], o[h]);
            if (k == 0) {
#pragma unroll
                for (int h = 0; h < 16; h++) p[h] = fmaf(y, sco[c * HID + h], p[h]);
            }
        }
    }
#pragma unroll
    for (int h = 0; h < 16; h++) { SB[base + h] = o[h]; SA[base + h] = p[h]; }
}

// ---------------- GL: fused (L@X) GEMM + pointwise epilogue -----------------
// mode 0: gl = GL(X); O1 = gl; O2 = A1 + 2*gl          (X=cur, A1=prev2)
// mode 1: gl = GL(X); O1 = A1 + 0.5*A2 + 0.5*gl        (X=u,  A1=cur, A2=t)
__global__ void __launch_bounds__(256) k_gl(
    const float* __restrict__ X, const float* __restrict__ A1,
    const float* __restrict__ A2,
    float* __restrict__ O1, float* __restrict__ O2,
    const float* __restrict__ w1, const float* __restrict__ w2,
    const float* __restrict__ w3, const float* __restrict__ b3, int mode)
{
    __shared__ __align__(16) float As[16][72];
    __shared__ __align__(16) float Bs[16][72];
    __shared__ float o1s[64][72];
    __shared__ float sw1[256], sw2[256], sw3[256], sb3[16];
    int tid = threadIdx.x;
    sw1[tid] = w1[tid]; sw2[tid] = w2[tid]; sw3[tid] = w3[tid];
    if (tid < 16) sb3[tid] = b3[tid];
    int tx = tid & 15, ty = tid >> 4;
    int row0 = blockIdx.y << 6, col0 = blockIdx.x << 6;
    int a_r = tid >> 2, a_c4 = (tid & 3) << 2;
    int b_r = tid >> 4, b_c4 = (tid & 15) << 2;
    ull acc[4][2];
#pragma unroll
    for (int i = 0; i < 4; i++) { acc[i][0] = pack2(0.f, 0.f); acc[i][1] = pack2(0.f, 0.f); }
    const float* Ap = g_L + (size_t)(row0 + a_r) * NP + a_c4;
    const float* Bp = X + (size_t)b_r * BH + col0 + b_c4;
    for (int k0 = 0; k0 < NP; k0 += 16) {
        float4 av = *(const float4*)(Ap + k0);
        As[a_c4 + 0][a_r] = av.x; As[a_c4 + 1][a_r] = av.y;
        As[a_c4 + 2][a_r] = av.z; As[a_c4 + 3][a_r] = av.w;
        *(float4*)(&Bs[b_r][b_c4]) = *(const float4*)(Bp + (size_t)k0 * BH);
        __syncthreads();
#pragma unroll
        for (int kk = 0; kk < 16; kk++) {
            float4 a = *(const float4*)(&As[kk][ty << 2]);
            ulonglong2 bb = *(const ulonglong2*)(&Bs[kk][tx << 2]);
            ull a0 = pack2(a.x, a.x), a1 = pack2(a.y, a.y);
            ull a2 = pack2(a.z, a.z), a3 = pack2(a.w, a.w);
            acc[0][0] = fma2(a0, bb.x, acc[0][0]); acc[0][1] = fma2(a0, bb.y, acc[0][1]);
            acc[1][0] = fma2(a1, bb.x, acc[1][0]); acc[1][1] = fma2(a1, bb.y, acc[1][1]);
            acc[2][0] = fma2(a2, bb.x, acc[2][0]); acc[2][1] = fma2(a2, bb.y, acc[2][1]);
            acc[3][0] = fma2(a3, bb.x, acc[3][0]); acc[3][1] = fma2(a3, bb.y, acc[3][1]);
        }
        __syncthreads();
    }
#pragma unroll
    for (int i = 0; i < 4; i++) {
        float v[4];
        unpack2(acc[i][0], v[0], v[1]);
        unpack2(acc[i][1], v[2], v[3]);
        int r = (ty << 2) + i, c = (tx << 2);
        o1s[r][c + 0] = v[0]; o1s[r][c + 1] = v[1];
        o1s[r][c + 2] = v[2]; o1s[r][c + 3] = v[3];
    }
    __syncthreads();
    // epilogue: thread -> (row nl, b-group bl) ; 64 rows x 4 groups of 16 h
    int nl = tid >> 2, bl = tid & 3;
    int n = row0 + nl;
    size_t base = (size_t)n * BH + col0 + (bl << 4);
    float xv[16];
    const float4* xp = (const float4*)(X + base);
#pragma unroll
    for (int q = 0; q < 4; q++) {
        float4 t = xp[q];
        xv[4 * q + 0] = t.x; xv[4 * q + 1] = t.y; xv[4 * q + 2] = t.z; xv[4 * q + 3] = t.w;
    }
    float a1v[16];
#pragma unroll 4
    for (int p = 0; p < 16; p++) {
        float s = 0.f;
#pragma unroll
        for (int h = 0; h < 16; h++) s = fmaf(xv[h], sw1[h * 16 + p], s);
        a1v[p] = ftanh(s);
    }
    float a2v[16];
#pragma unroll 4
    for (int p = 0; p < 16; p++) {
        float s = 0.f;
#pragma unroll
        for (int h = 0; h < 16; h++) s = fmaf(a1v[h], sw2[h * 16 + p], s);
        a2v[p] = ftanh(s);
    }
    float rr[16];
#pragma unroll
    for (int h = 0; h < 16; h++) rr[h] = o1s[nl][(bl << 4) + h] - a2v[h];
    if (mode == 0) {
#pragma unroll 4
        for (int p = 0; p < 16; p++) {
            float s = sb3[p];
#pragma unroll
            for (int h = 0; h < 16; h++) s = fmaf(rr[h], sw3[h * 16 + p], s);
            O1[base + p] = s;
            O2[base + p] = A1[base + p] + 2.0f * s;
        }
    } else {
#pragma unroll 4
        for (int p = 0; p < 16; p++) {
            float s = sb3[p];
#pragma unroll
            for (int h = 0; h < 16; h++) s = fmaf(rr[h], sw3[h * 16 + p], s);
            O1[base + p] = A1[base + p] + 0.5f * A2[base + p] + 0.5f * s;
        }
    }
}

// ---------------- NL: fully fused 10-step LSTM-cell chain -------------------
__device__ __forceinline__ void nl_eval(
    const float* x, float* out,
    const float* sW, const float* sb, const float* sw2)
{
    float acc[16];
#pragma unroll
    for (int h = 0; h < 16; h++) acc[h] = 0.f;
#pragma unroll 4
    for (int p = 0; p < 32; p++) {
        float gi = sb[p], gg = sb[64 + p], go = sb[96 + p];
#pragma unroll
        for (int h = 0; h < 16; h++) {
            float xh = x[h];
            gi = fmaf(xh, sW[h * 128 + p], gi);
            gg = fmaf(xh, sW[h * 128 + 64 + p], gg);
            go = fmaf(xh, sW[h * 128 + 96 + p], go);
        }
        float c = fsig(gi) * ftanh(gg);
        float hh = fsig(go) * ftanh(c);
        float th = ftanh(hh);
#pragma unroll
        for (int h = 0; h < 16; h++) acc[h] = fmaf(th, sw2[p * 16 + h], acc[h]);
    }
#pragma unroll
    for (int h = 0; h < 16; h++) out[h] = acc[h];
}

__global__ void __launch_bounds__(128) k_nl(
    const float* __restrict__ S0, const float* __restrict__ S1,
    const float* __restrict__ Wih, const float* __restrict__ lb,
    const float* __restrict__ w2, const float* __restrict__ cw,
    const float* __restrict__ cb, const float* __restrict__ c1w,
    const float* __restrict__ c1b, float* __restrict__ out)
{
    __shared__ float sW[16 * 128];
    __shared__ float sb[128];
    __shared__ float sw2[32 * 16];
    __shared__ float scw[256], sc1w[256], scb[16], sc1b[16];
    int tid = threadIdx.x;
    for (int i = tid; i < 2048; i += 128) sW[i] = Wih[i];
    sb[tid] = lb[tid];
    for (int i = tid; i < 512; i += 128) sw2[i] = w2[i];
    for (int i = tid; i < 256; i += 128) { scw[i] = cw[i]; sc1w[i] = c1w[i]; }
    if (tid < 16) { scb[tid] = cb[tid]; sc1b[tid] = c1b[tid]; }
    __syncthreads();

    int idx = blockIdx.x * 128 + tid;        // grid sized exactly NNODE*BATCH
    int n = idx >> 9, b = idx & 511;
    size_t base = (size_t)n * BH + ((size_t)b << 4);
    float s0[16], s1[16];
#pragma unroll
    for (int q = 0; q < 4; q++) {
        float4 t0 = *(const float4*)(S0 + base + 4 * q);
        float4 t1 = *(const float4*)(S1 + base + 4 * q);
        s0[4 * q + 0] = t0.x; s0[4 * q + 1] = t0.y; s0[4 * q + 2] = t0.z; s0[4 * q + 3] = t0.w;
        s1[4 * q + 0] = t1.x; s1[4 * q + 1] = t1.y; s1[4 * q + 2] = t1.z; s1[4 * q + 3] = t1.w;
    }
    // step_00 = s0 @ c_w + c_b ; step_11 = s1 @ c1_w + c1_b
    float s00[16], s11[16];
#pragma unroll 4
    for (int p = 0; p < 16; p++) {
        float a = scb[p], d = sc1b[p];
#pragma unroll
        for (int h = 0; h < 16; h++) {
            a = fmaf(s0[h], scw[h * 16 + p], a);
            d = fmaf(s1[h], sc1w[h * 16 + p], d);
        }
        s00[p] = a; s11[p] = d;
    }
    float* op = out + (((size_t)b * NNODE + n) * 10) * HID;
    float t[16], tmp[16], g[16], p2[16];
    // first step
    nl_eval(s11, t, sW, sb, sw2);
#pragma unroll
    for (int h = 0; h < 16; h++) tmp[h] = fmaf(2.0f, t[h], s00[h]);
    nl_eval(tmp, tmp, sW, sb, sw2);
#pragma unroll
    for (int h = 0; h < 16; h++) {
        g[h] = fmaf(0.5f, t[h], s1[h]) + 0.5f * tmp[h];
        p2[h] = s11[h];
    }
#pragma unroll
    for (int q = 0; q < 4; q++)
        *(float4*)(op + 4 * q) = make_float4(g[4 * q], g[4 * q + 1], g[4 * q + 2], g[4 * q + 3]);
    // 9 more
    for (int j = 1; j < 10; j++) {
        nl_eval(g, t, sW, sb, sw2);
#pragma unroll
        for (int h = 0; h < 16; h++) tmp[h] = fmaf(2.0f, t[h], p2[h]);
        nl_eval(tmp, tmp, sW, sb, sw2);
#pragma unroll
        for (int h = 0; h < 16; h++) {
            float nw = fmaf(0.5f, t[h], g[h]) + 0.5f * tmp[h];
            p2[h] = g[h];
            g[h] = nw;
        }
        float* oj = op + (size_t)j * HID;
#pragma unroll
        for (int q = 0; q < 4; q++)
            *(float4*)(oj + 4 * q) = make_float4(g[4 * q], g[4 * q + 1], g[4 * q + 2], g[4 * q + 3]);
    }
}

// ------------------------------ launch --------------------------------------
extern "C" void kernel_launch(void* const* d_in, const int* in_sizes, int n_in,
                              void* d_out, int out_size) {
    const float* flow    = (const float*)d_in[0];
    const float* nodeemb = (const float*)d_in[1];
    const float* cheb_w  = (const float*)d_in[2];
    const float* cheb_b  = (const float*)d_in[3];
    const float* cou_w   = (const float*)d_in[4];
    const float* gl_out  = (const float*)d_in[5];
    const float* gl_fk   = (const float*)d_in[6];
    const float* gl_tz_w = (const float*)d_in[7];
    const float* gl_tz_b = (const float*)d_in[8];
    const float* lstmW   = (const float*)d_in[9];
    const float* lstmb   = (const float*)d_in[10];
    const float* nl_w2   = (const float*)d_in[11];
    const float* c_w     = (const float*)d_in[12];
    const float* c_b     = (const float*)d_in[13];
    const float* c1_w    = (const float*)d_in[14];
    const float* c1_b    = (const float*)d_in[15];

    float *Y, *SA, *SB, *T, *U;
    cudaGetSymbolAddress((void**)&Y,  g_Y);
    cudaGetSymbolAddress((void**)&SA, g_SA);
    cudaGetSymbolAddress((void**)&SB, g_SB);
    cudaGetSymbolAddress((void**)&T,  g_T);
    cudaGetSymbolAddress((void**)&U,  g_U);

    k_norm<<<5, 64>>>(nodeemb);
    k_gram<<<NNODE, 64>>>();
    k_lap<<<(NP * NP + 255) / 256, 256>>>();
    k_xt<<<(NP * BATCH + 127) / 128, 128>>>(flow, Y);

    // Chebyshev feature recurrence
    k_gemm<<<dim3(BC / 64, NP / 64), 256>>>(Y, Y, Y + NPBC, BC, 1.f, 0.f);
    for (int k = 2; k < KORD; k++)
        k_gemm<<<dim3(BC / 64, NP / 64), 256>>>(
            Y + (size_t)(k - 1) * NPBC, Y + (size_t)(k - 2) * NPBC,
            Y + (size_t)k * NPBC, BC, 2.f, -1.f);

    k_combine<<<(NP * BATCH + 127) / 128, 128>>>(cheb_w, cheb_b, cou_w, Y, SA, SB);

    // GL diffusion chain: prev2 = SA (out), cur = SB (output)
    float* p = SA;
    float* c = SB;
    for (int it = 0; it < 10; it++) {
        k_gl<<<dim3(BH / 64, NP / 64), 256>>>(c, p, p, T, U,
                                              gl_out, gl_fk, gl_tz_w, gl_tz_b, 0);
        k_gl<<<dim3(BH / 64, NP / 64), 256>>>(U, c, T, p, T,
                                              gl_out, gl_fk, gl_tz_w, gl_tz_b, 1);
        float* tmpp = p; p = c; c = tmpp;
    }
    // after 10 iters: step_0 = p, step_1 = c

    k_nl<<<(NNODE * BATCH) / 128, 128>>>(p, c, lstmW, lstmb, nl_w2,
                                         c_w, c_b, c1_w, c1_b, (float*)d_out);
}